// round 2
// baseline (speedup 1.0000x reference)
#include <cuda_runtime.h>

// ---------------------------------------------------------------------------
// Problem constants
// ---------------------------------------------------------------------------
#define BB   2
#define HH   12
#define DD   64
#define EE   768
#define QLL  1024
#define KLL  2048
#define HDD  768           // H*D
#define SCALEF 0.125f      // 1/sqrt(64)

// Harness widens the JAX bool mask to int32 (its dtype set is f32/i32/bf16).
typedef int mask_t;

// ---------------------------------------------------------------------------
// Scratch (device globals: allocation inside kernel_launch is forbidden)
// ---------------------------------------------------------------------------
__device__ float g_q  [(size_t)BB * QLL * HDD];
__device__ float g_k  [(size_t)BB * KLL * HDD];
__device__ float g_v  [(size_t)BB * KLL * HDD];
__device__ float g_r  [(size_t)KLL * HDD];
__device__ float g_s  [(size_t)BB * HH * QLL * KLL];   // scores (201 MB)
__device__ float g_vec[(size_t)BB * QLL * HDD];

// ---------------------------------------------------------------------------
// Generic tiled GEMM: C[M,N] = A[M,K] @ W[K,N] + bias   (64x64 tile, 4x4/thread)
// Requires M%64==0, N%64==0, K%16==0 (true for all uses here).
// ---------------------------------------------------------------------------
__global__ __launch_bounds__(256)
void gemm_bias(const float* __restrict__ A, const float* __restrict__ W,
               const float* __restrict__ bias, float* __restrict__ C,
               int M, int N, int K)
{
    __shared__ float As[16][65];
    __shared__ float Ws[16][65];

    const int tid = threadIdx.x;
    const int tr  = tid >> 4;      // 0..15
    const int tc  = tid & 15;      // 0..15
    const int m0  = blockIdx.y * 64;
    const int n0  = blockIdx.x * 64;

    float acc[4][4] = {};

    for (int k0 = 0; k0 < K; k0 += 16) {
        // A tile (64 x 16), transposed into As[k][m]; coalesced over k
        {
            const int kk = tid & 15;
            const int mb = tid >> 4;
            #pragma unroll
            for (int i = 0; i < 4; i++) {
                const int m = mb + i * 16;
                As[kk][m] = A[(size_t)(m0 + m) * K + k0 + kk];
            }
        }
        // W tile (16 x 64); coalesced over n
        {
            const int n  = tid & 63;
            const int kb = tid >> 6;
            #pragma unroll
            for (int i = 0; i < 4; i++) {
                const int kk = kb + i * 4;
                Ws[kk][n] = W[(size_t)(k0 + kk) * N + n0 + n];
            }
        }
        __syncthreads();

        #pragma unroll
        for (int kk = 0; kk < 16; kk++) {
            float a[4], w[4];
            #pragma unroll
            for (int i = 0; i < 4; i++) a[i] = As[kk][tr * 4 + i];
            #pragma unroll
            for (int j = 0; j < 4; j++) w[j] = Ws[kk][tc * 4 + j];
            #pragma unroll
            for (int i = 0; i < 4; i++)
                #pragma unroll
                for (int j = 0; j < 4; j++)
                    acc[i][j] += a[i] * w[j];
        }
        __syncthreads();
    }

    #pragma unroll
    for (int i = 0; i < 4; i++) {
        const int m = m0 + tr * 4 + i;
        #pragma unroll
        for (int j = 0; j < 4; j++) {
            const int n = n0 + tc * 4 + j;
            const float bb = bias ? bias[n] : 0.0f;
            C[(size_t)m * N + n] = acc[i][j] + bb;
        }
    }
}

// ---------------------------------------------------------------------------
// Score kernel: S[b3,h3,q,k] = (AC + BD_shifted)*SCALE, masked -> -1e9.
//
// rel_shift analysis: with m' = b3*H + h3 + B,
//   b_ = m'/(H+1), hh = m'%(H+1);  BD_shifted = 0 if hh==0
//   else BD evaluated at (batch=b_, head=hh-1).
// So each tile is a 64x64x128 GEMM:
//   A'[q, 0:64]   = q[b3,q,h3,:]  + r_w_bias[h3,:]
//   A'[q, 64:128] = q[b_,q,hm1,:] + r_r_bias[hm1,:]  (or 0)
//   B'[k, 0:64]   = k[b3,k,h3,:]
//   B'[k, 64:128] = r[k,hm1,:]                        (or 0)
// ---------------------------------------------------------------------------
__global__ __launch_bounds__(256)
void score_kernel(const float* __restrict__ rwb, const float* __restrict__ rrb,
                  const mask_t* __restrict__ mask)
{
    const int bh = blockIdx.z;             // b3*H + h3
    const int b3 = bh / HH;
    const int h3 = bh % HH;
    const int mprime = bh + BB;
    const int b_u = mprime / (HH + 1);
    const int hh  = mprime % (HH + 1);
    const bool has_bd = (hh != 0);
    const int hm1 = hh - 1;

    const int q0  = blockIdx.y * 64;
    const int k0c = blockIdx.x * 64;

    __shared__ float As[16][65];
    __shared__ float Bs[16][65];

    const int tid = threadIdx.x;
    const int tr  = tid >> 4;
    const int tc  = tid & 15;

    float acc[4][4] = {};

    for (int kd0 = 0; kd0 < 128; kd0 += 16) {
        // A' tile
        {
            const int kk = tid & 15;
            const int dd = kd0 + kk;
            const int mb = tid >> 4;
            #pragma unroll
            for (int i = 0; i < 4; i++) {
                const int m = mb + i * 16;
                float v;
                if (dd < 64) {
                    v = g_q[(size_t)(b3 * QLL + q0 + m) * HDD + h3 * DD + dd]
                        + rwb[h3 * DD + dd];
                } else if (has_bd) {
                    const int d2 = dd - 64;
                    v = g_q[(size_t)(b_u * QLL + q0 + m) * HDD + hm1 * DD + d2]
                        + rrb[hm1 * DD + d2];
                } else {
                    v = 0.0f;
                }
                As[kk][m] = v;
            }
        }
        // B' tile
        {
            const int kk = tid & 15;
            const int dd = kd0 + kk;
            const int nb = tid >> 4;
            #pragma unroll
            for (int i = 0; i < 4; i++) {
                const int n = nb + i * 16;
                float v;
                if (dd < 64) {
                    v = g_k[(size_t)(b3 * KLL + k0c + n) * HDD + h3 * DD + dd];
                } else if (has_bd) {
                    v = g_r[(size_t)(k0c + n) * HDD + hm1 * DD + (dd - 64)];
                } else {
                    v = 0.0f;
                }
                Bs[kk][n] = v;
            }
        }
        __syncthreads();

        #pragma unroll
        for (int kk = 0; kk < 16; kk++) {
            float a[4], b[4];
            #pragma unroll
            for (int i = 0; i < 4; i++) a[i] = As[kk][tr * 4 + i];
            #pragma unroll
            for (int j = 0; j < 4; j++) b[j] = Bs[kk][tc * 4 + j];
            #pragma unroll
            for (int i = 0; i < 4; i++)
                #pragma unroll
                for (int j = 0; j < 4; j++)
                    acc[i][j] += a[i] * b[j];
        }
        __syncthreads();
    }

    #pragma unroll
    for (int i = 0; i < 4; i++) {
        const int q = q0 + tr * 4 + i;
        #pragma unroll
        for (int j = 0; j < 4; j++) {
            const int k = k0c + tc * 4 + j;
            const bool msk = mask[(size_t)(b3 * QLL + q) * KLL + k] != 0;
            g_s[((size_t)bh * QLL + q) * KLL + k] = msk ? -1e9f : acc[i][j] * SCALEF;
        }
    }
}

// ---------------------------------------------------------------------------
// Softmax: one block per (b,h,q) row of 2048; values stay in registers.
// ---------------------------------------------------------------------------
__device__ __forceinline__ float warp_max(float v) {
    #pragma unroll
    for (int o = 16; o; o >>= 1) v = fmaxf(v, __shfl_xor_sync(0xffffffffu, v, o));
    return v;
}
__device__ __forceinline__ float warp_sum(float v) {
    #pragma unroll
    for (int o = 16; o; o >>= 1) v += __shfl_xor_sync(0xffffffffu, v, o);
    return v;
}

__global__ __launch_bounds__(256)
void softmax_kernel(const float* __restrict__ S, float* __restrict__ P)
{
    const size_t row = blockIdx.x;
    const float* s = S + row * KLL;
    float*       p = P + row * KLL;

    __shared__ float sh[8];
    const int wid = threadIdx.x >> 5;
    const int lid = threadIdx.x & 31;

    float v[8];
    float m = -3.0e38f;
    #pragma unroll
    for (int i = 0; i < 8; i++) {
        v[i] = s[threadIdx.x + i * 256];
        m = fmaxf(m, v[i]);
    }
    float wm = warp_max(m);
    if (lid == 0) sh[wid] = wm;
    __syncthreads();
    if (wid == 0) {
        float t = (lid < 8) ? sh[lid] : -3.0e38f;
        t = warp_max(t);
        if (lid == 0) sh[0] = t;
    }
    __syncthreads();
    const float bm = sh[0];

    float lsum = 0.0f;
    #pragma unroll
    for (int i = 0; i < 8; i++) {
        v[i] = __expf(v[i] - bm);
        lsum += v[i];
    }
    float ws = warp_sum(lsum);
    __syncthreads();
    if (lid == 0) sh[wid] = ws;
    __syncthreads();
    if (wid == 0) {
        float t = (lid < 8) ? sh[lid] : 0.0f;
        t = warp_sum(t);
        if (lid == 0) sh[0] = t;
    }
    __syncthreads();
    const float inv = 1.0f / sh[0];

    #pragma unroll
    for (int i = 0; i < 8; i++)
        p[threadIdx.x + i * 256] = v[i] * inv;
}

// ---------------------------------------------------------------------------
// PV: per (b,h): vec(1024x64) = prob(1024x2048) @ V_h(2048x64)
// ---------------------------------------------------------------------------
__global__ __launch_bounds__(256)
void pv_kernel(const float* __restrict__ prob)
{
    const int bh = blockIdx.z;
    const int b3 = bh / HH;
    const int h3 = bh % HH;
    const int q0 = blockIdx.y * 64;

    __shared__ float As[16][65];
    __shared__ float Bs[16][65];

    const int tid = threadIdx.x;
    const int tr  = tid >> 4;
    const int tc  = tid & 15;

    const float* P = prob + (size_t)bh * QLL * KLL;

    float acc[4][4] = {};

    for (int k0 = 0; k0 < KLL; k0 += 16) {
        {
            const int kk = tid & 15;
            const int mb = tid >> 4;
            #pragma unroll
            for (int i = 0; i < 4; i++) {
                const int m = mb + i * 16;
                As[kk][m] = P[(size_t)(q0 + m) * KLL + k0 + kk];
            }
        }
        {
            const int n  = tid & 63;
            const int kb = tid >> 6;
            #pragma unroll
            for (int i = 0; i < 4; i++) {
                const int kk = kb + i * 4;
                Bs[kk][n] = g_v[(size_t)(b3 * KLL + k0 + kk) * HDD + h3 * DD + n];
            }
        }
        __syncthreads();

        #pragma unroll
        for (int kk = 0; kk < 16; kk++) {
            float a[4], b[4];
            #pragma unroll
            for (int i = 0; i < 4; i++) a[i] = As[kk][tr * 4 + i];
            #pragma unroll
            for (int j = 0; j < 4; j++) b[j] = Bs[kk][tc * 4 + j];
            #pragma unroll
            for (int i = 0; i < 4; i++)
                #pragma unroll
                for (int j = 0; j < 4; j++)
                    acc[i][j] += a[i] * b[j];
        }
        __syncthreads();
    }

    #pragma unroll
    for (int i = 0; i < 4; i++) {
        const int q = q0 + tr * 4 + i;
        #pragma unroll
        for (int j = 0; j < 4; j++) {
            const int n = tc * 4 + j;
            g_vec[(size_t)(b3 * QLL + q) * HDD + h3 * DD + n] = acc[i][j];
        }
    }
}

// ---------------------------------------------------------------------------
// Launch
// ---------------------------------------------------------------------------
extern "C" void kernel_launch(void* const* d_in, const int* in_sizes, int n_in,
                              void* d_out, int out_size)
{
    (void)in_sizes; (void)n_in; (void)out_size;

    const float*  Q    = (const float*)d_in[0];
    const float*  Kin  = (const float*)d_in[1];
    const float*  Vin  = (const float*)d_in[2];
    const float*  pos  = (const float*)d_in[3];
    const float*  rwb  = (const float*)d_in[4];
    const float*  rrb  = (const float*)d_in[5];
    const mask_t* mask = (const mask_t*)d_in[6];
    // d_in[7] = mems, unused by the forward pass
    const float*  Wq = (const float*)d_in[8];
    const float*  bq = (const float*)d_in[9];
    const float*  Wk = (const float*)d_in[10];
    const float*  bk = (const float*)d_in[11];
    const float*  Wv = (const float*)d_in[12];
    const float*  bv = (const float*)d_in[13];
    const float*  Wr = (const float*)d_in[14];
    const float*  Wo = (const float*)d_in[15];
    const float*  bo = (const float*)d_in[16];

    float* out  = (float*)d_out;                       // (B, QL, E)
    float* prob = out + (size_t)BB * QLL * EE;         // (B, H, QL, KL)

    float *pq, *pk, *pv, *pr, *ps, *pvec;
    cudaGetSymbolAddress((void**)&pq,   g_q);
    cudaGetSymbolAddress((void**)&pk,   g_k);
    cudaGetSymbolAddress((void**)&pv,   g_v);
    cudaGetSymbolAddress((void**)&pr,   g_r);
    cudaGetSymbolAddress((void**)&ps,   g_s);
    cudaGetSymbolAddress((void**)&pvec, g_vec);

    const dim3 blk(256);

    // Projections
    gemm_bias<<<dim3(HDD / 64, (BB * QLL) / 64), blk>>>(Q,   Wq, bq,      pq, BB * QLL, HDD, EE);
    gemm_bias<<<dim3(HDD / 64, (BB * KLL) / 64), blk>>>(Kin, Wk, bk,      pk, BB * KLL, HDD, EE);
    gemm_bias<<<dim3(HDD / 64, (BB * KLL) / 64), blk>>>(Vin, Wv, bv,      pv, BB * KLL, HDD, EE);
    gemm_bias<<<dim3(HDD / 64, KLL / 64),        blk>>>(pos, Wr, nullptr, pr, KLL,      HDD, EE);

    // Scores (AC + rel-shifted BD, masked, scaled)
    score_kernel<<<dim3(KLL / 64, QLL / 64, BB * HH), blk>>>(rwb, rrb, mask);

    // Softmax -> prob output region
    softmax_kernel<<<BB * HH * QLL, blk>>>(ps, prob);

    // prob @ V -> vec
    pv_kernel<<<dim3(1, QLL / 64, BB * HH), blk>>>(prob);

    // Output projection
    gemm_bias<<<dim3(EE / 64, (BB * QLL) / 64), blk>>>(pvec, Wo, bo, out, BB * QLL, EE, HDD);
}

// round 4
// speedup vs baseline: 2.1923x; 2.1923x over previous
#include <cuda_runtime.h>
#include <cuda_bf16.h>
#include <stdint.h>

// ---------------------------------------------------------------------------
// Problem constants
// ---------------------------------------------------------------------------
#define BB   2
#define HH   12
#define DD   64
#define EE   768
#define QLL  1024
#define KLL  2048
#define HDD  768
#define SCALEF 0.125f
typedef int mask_t;   // harness widens bool -> int32

// ---------------------------------------------------------------------------
// Scratch (device globals)
// ---------------------------------------------------------------------------
__device__ float g_q  [(size_t)BB * QLL * HDD];
__device__ float g_k  [(size_t)BB * KLL * HDD];
__device__ float g_v  [(size_t)BB * KLL * HDD];
__device__ float g_r  [(size_t)KLL * HDD];
__device__ float g_s  [(size_t)BB * HH * QLL * KLL];
__device__ float g_vec[(size_t)BB * QLL * HDD];

// ---------------------------------------------------------------------------
// Warp-level tensor-core primitives (plain sm_103 target: mma.sync + ldmatrix)
// ---------------------------------------------------------------------------
__device__ __forceinline__ uint32_t smem_u32(const void* p) {
    uint32_t a;
    asm("{ .reg .u64 t; cvta.to.shared.u64 t, %1; cvt.u32.u64 %0, t; }" : "=r"(a) : "l"(p));
    return a;
}

__device__ __forceinline__ void ldsm4(uint32_t& r0, uint32_t& r1, uint32_t& r2, uint32_t& r3,
                                      uint32_t a) {
    asm volatile("ldmatrix.sync.aligned.m8n8.x4.shared.b16 {%0,%1,%2,%3}, [%4];"
                 : "=r"(r0), "=r"(r1), "=r"(r2), "=r"(r3) : "r"(a));
}

__device__ __forceinline__ void mma16816(float* c, const uint32_t* a, const uint32_t* b) {
    asm volatile("mma.sync.aligned.m16n8k16.row.col.f32.bf16.bf16.f32 "
                 "{%0,%1,%2,%3}, {%4,%5,%6,%7}, {%8,%9}, {%0,%1,%2,%3};"
                 : "+f"(c[0]), "+f"(c[1]), "+f"(c[2]), "+f"(c[3])
                 : "r"(a[0]), "r"(a[1]), "r"(a[2]), "r"(a[3]), "r"(b[0]), "r"(b[1]));
}

__device__ __forceinline__ void split_bf16(float x, unsigned short& h, unsigned short& l) {
    __nv_bfloat16 hb = __float2bfloat16(x);
    h = __bfloat16_as_ushort(hb);
    l = __bfloat16_as_ushort(__float2bfloat16(x - __bfloat162float(hb)));
}

// pack 4 floats into 4 bf16 (uint2)
__device__ __forceinline__ void split4(float4 v, uint2& hi, uint2& lo) {
    unsigned short h0, h1, h2, h3, l0, l1, l2, l3;
    split_bf16(v.x, h0, l0); split_bf16(v.y, h1, l1);
    split_bf16(v.z, h2, l2); split_bf16(v.w, h3, l3);
    hi = make_uint2((uint32_t)h0 | ((uint32_t)h1 << 16), (uint32_t)h2 | ((uint32_t)h3 << 16));
    lo = make_uint2((uint32_t)l0 | ((uint32_t)l1 << 16), (uint32_t)l2 | ((uint32_t)l3 << 16));
}

// ---------------------------------------------------------------------------
// Generic batched GEMM: C[M,N] = A[M,K] * B^T + bias
//   A row-major (lda); B element (n,k) at B[k*ldb + n]; C row-major (ldc).
//   Block tile 128x64, K-slab 64, 8 warps (4m x 2n), warp tile 32x32.
//   smem pitch = 144 bytes/row (72 bf16): 16B-aligned rows, 4-bank shift/row.
// ---------------------------------------------------------------------------
#define GP 144      // smem row pitch (bytes) for 64-col slabs
#define SM_AHI 0
#define SM_ALO (128 * GP)                  // 18432
#define SM_BHI (2 * 128 * GP)              // 36864
#define SM_BLO (2 * 128 * GP + 64 * GP)    // 46080
#define SM_G_TOTAL (2 * 128 * GP + 2 * 64 * GP)  // 55296

__global__ void __launch_bounds__(256, 2)
tgemm(const float* __restrict__ Ag, long lda, long sAb, long sAh,
      const float* __restrict__ Bg, long ldb, long sBb, long sBh,
      const float* __restrict__ bias,
      float* __restrict__ Cg, long ldc, long sCb, long sCh,
      int K, int nh)
{
    extern __shared__ char sm[];
    const uint32_t sb = smem_u32(sm);
    const int tid = threadIdx.x, wid = tid >> 5, lane = tid & 31;
    const int mw = wid >> 1, nw = wid & 1;
    const int zb = blockIdx.z / nh, zh = blockIdx.z % nh;
    const float* A = Ag + (size_t)zb * sAb + (size_t)zh * sAh;
    const float* B = Bg + (size_t)zb * sBb + (size_t)zh * sBh;
    float*       C = Cg + (size_t)zb * sCb + (size_t)zh * sCh;
    const int m0 = blockIdx.y << 7;
    const int n0 = blockIdx.x << 6;

    float acc[2][4][4] = {};

    const int nslab = K >> 6;
    for (int s = 0; s < nslab; s++) {
        const int k0 = s << 6;
        // A slab: 128x64 floats, float4 over k
        #pragma unroll
        for (int it = 0; it < 8; it++) {
            int idx = (it * 256 + tid) << 2;
            int m = idx >> 6, k = idx & 63;
            float4 a = *reinterpret_cast<const float4*>(A + (size_t)(m0 + m) * lda + (k0 + k));
            uint2 hi, lo; split4(a, hi, lo);
            int off = m * GP + k * 2;
            *reinterpret_cast<uint2*>(sm + SM_AHI + off) = hi;
            *reinterpret_cast<uint2*>(sm + SM_ALO + off) = lo;
        }
        // B slab: 64 n x 64 k, element (n,k) = B[(k0+k)*ldb + n0+n], coalesced over n
        #pragma unroll
        for (int it = 0; it < 16; it++) {
            int idx = it * 256 + tid;
            int k = idx >> 6, n = idx & 63;
            float b = B[(size_t)(k0 + k) * ldb + (n0 + n)];
            unsigned short h, l; split_bf16(b, h, l);
            int off = n * GP + k * 2;
            *reinterpret_cast<unsigned short*>(sm + SM_BHI + off) = h;
            *reinterpret_cast<unsigned short*>(sm + SM_BLO + off) = l;
        }
        __syncthreads();

        #pragma unroll
        for (int ks = 0; ks < 4; ks++) {
            const int kc = ks << 4;
            uint32_t ah[2][4], al[2][4], bh[4][2], bl[4][2];
            #pragma unroll
            for (int i = 0; i < 2; i++) {
                int row = mw * 32 + i * 16 + (lane & 15);
                int col = kc + ((lane >> 4) << 3);
                uint32_t off = (uint32_t)(row * GP + col * 2);
                ldsm4(ah[i][0], ah[i][1], ah[i][2], ah[i][3], sb + SM_AHI + off);
                ldsm4(al[i][0], al[i][1], al[i][2], al[i][3], sb + SM_ALO + off);
            }
            #pragma unroll
            for (int jj = 0; jj < 2; jj++) {
                int n = nw * 32 + jj * 16 + ((lane >> 4) << 3) + (lane & 7);
                int k = kc + (((lane >> 3) & 1) << 3);
                uint32_t off = (uint32_t)(n * GP + k * 2);
                ldsm4(bh[jj*2][0], bh[jj*2][1], bh[jj*2+1][0], bh[jj*2+1][1], sb + SM_BHI + off);
                ldsm4(bl[jj*2][0], bl[jj*2][1], bl[jj*2+1][0], bl[jj*2+1][1], sb + SM_BLO + off);
            }
            #pragma unroll
            for (int i = 0; i < 2; i++)
                #pragma unroll
                for (int j = 0; j < 4; j++) {
                    mma16816(acc[i][j], ah[i], bh[j]);
                    mma16816(acc[i][j], ah[i], bl[j]);
                    mma16816(acc[i][j], al[i], bh[j]);
                }
        }
        __syncthreads();
    }

    // Epilogue
    const int gid = lane >> 2, tg = lane & 3;
    #pragma unroll
    for (int i = 0; i < 2; i++)
        #pragma unroll
        for (int j = 0; j < 4; j++) {
            int r = m0 + mw * 32 + i * 16 + gid;
            int c = n0 + nw * 32 + j * 8 + tg * 2;
            float b0 = bias ? bias[c] : 0.f;
            float b1 = bias ? bias[c + 1] : 0.f;
            *reinterpret_cast<float2*>(C + (size_t)r * ldc + c) =
                make_float2(acc[i][j][0] + b0, acc[i][j][1] + b1);
            *reinterpret_cast<float2*>(C + (size_t)(r + 8) * ldc + c) =
                make_float2(acc[i][j][2] + b0, acc[i][j][3] + b1);
        }
}

// ---------------------------------------------------------------------------
// Fused score kernel: 128 q-rows resident (A' = [q+rwb | q'+rrb], 128 d-cols),
// loop 32 key-tiles of 64; B' = [k | r]; epilogue mask+scale -> g_s.
// rel_shift remap: m' = bh + B; bu = m'/(H+1); hh = m'%(H+1);
//                  BD term absent if hh==0 else uses head hh-1 / batch bu.
// smem pitch 272 bytes/row (136 bf16).
// ---------------------------------------------------------------------------
#define SP 272
#define SS_AHI 0
#define SS_ALO (128 * SP)                   // 34816
#define SS_BHI (2 * 128 * SP)               // 69632
#define SS_BLO (2 * 128 * SP + 64 * SP)     // 87040
#define SS_TOTAL (2 * 128 * SP + 2 * 64 * SP)   // 104448

__global__ void __launch_bounds__(256, 2)
tscore(const float* __restrict__ rwb, const float* __restrict__ rrb,
       const mask_t* __restrict__ mask)
{
    extern __shared__ char sm[];
    const uint32_t sb = smem_u32(sm);
    const int tid = threadIdx.x, wid = tid >> 5, lane = tid & 31;
    const int mw = wid >> 1, nw = wid & 1;
    const int bh = blockIdx.z;
    const int b3 = bh / HH, h3 = bh % HH;
    const int mp = bh + BB;
    const int bu = mp / (HH + 1), hh = mp % (HH + 1);
    const int has_bd = (hh != 0);
    const int hm1 = hh - 1;
    const int q0 = blockIdx.y << 7;

    // A' fill (128 x 128)
    #pragma unroll
    for (int it = 0; it < 16; it++) {
        int idx = (it * 256 + tid) << 2;
        int m = idx >> 7, d = idx & 127;
        float4 v;
        if (d < 64) {
            v = *reinterpret_cast<const float4*>(&g_q[(size_t)(b3 * QLL + q0 + m) * HDD + h3 * DD + d]);
            float4 b = *reinterpret_cast<const float4*>(&rwb[h3 * DD + d]);
            v.x += b.x; v.y += b.y; v.z += b.z; v.w += b.w;
        } else if (has_bd) {
            int d2 = d - 64;
            v = *reinterpret_cast<const float4*>(&g_q[(size_t)(bu * QLL + q0 + m) * HDD + hm1 * DD + d2]);
            float4 b = *reinterpret_cast<const float4*>(&rrb[hm1 * DD + d2]);
            v.x += b.x; v.y += b.y; v.z += b.z; v.w += b.w;
        } else {
            v = make_float4(0.f, 0.f, 0.f, 0.f);
        }
        uint2 hi, lo; split4(v, hi, lo);
        int off = m * SP + d * 2;
        *reinterpret_cast<uint2*>(sm + SS_AHI + off) = hi;
        *reinterpret_cast<uint2*>(sm + SS_ALO + off) = lo;
    }

    const int gid = lane >> 2, tg = lane & 3;

    for (int kt = 0; kt < 32; kt++) {
        const int kc = kt << 6;
        // B' fill (64 keys x 128 d)
        #pragma unroll
        for (int it = 0; it < 8; it++) {
            int idx = (it * 256 + tid) << 2;
            int n = idx >> 7, d = idx & 127;
            float4 v;
            if (d < 64) {
                v = *reinterpret_cast<const float4*>(&g_k[(size_t)(b3 * KLL + kc + n) * HDD + h3 * DD + d]);
            } else if (has_bd) {
                v = *reinterpret_cast<const float4*>(&g_r[(size_t)(kc + n) * HDD + hm1 * DD + (d - 64)]);
            } else {
                v = make_float4(0.f, 0.f, 0.f, 0.f);
            }
            uint2 hi, lo; split4(v, hi, lo);
            int off = n * SP + d * 2;
            *reinterpret_cast<uint2*>(sm + SS_BHI + off) = hi;
            *reinterpret_cast<uint2*>(sm + SS_BLO + off) = lo;
        }
        __syncthreads();

        float acc[2][4][4] = {};
        #pragma unroll
        for (int ks = 0; ks < 8; ks++) {
            const int kcc = ks << 4;
            uint32_t ah[2][4], al[2][4], bh[4][2], bl[4][2];
            #pragma unroll
            for (int i = 0; i < 2; i++) {
                int row = mw * 32 + i * 16 + (lane & 15);
                int col = kcc + ((lane >> 4) << 3);
                uint32_t off = (uint32_t)(row * SP + col * 2);
                ldsm4(ah[i][0], ah[i][1], ah[i][2], ah[i][3], sb + SS_AHI + off);
                ldsm4(al[i][0], al[i][1], al[i][2], al[i][3], sb + SS_ALO + off);
            }
            #pragma unroll
            for (int jj = 0; jj < 2; jj++) {
                int n = nw * 32 + jj * 16 + ((lane >> 4) << 3) + (lane & 7);
                int k = kcc + (((lane >> 3) & 1) << 3);
                uint32_t off = (uint32_t)(n * SP + k * 2);
                ldsm4(bh[jj*2][0], bh[jj*2][1], bh[jj*2+1][0], bh[jj*2+1][1], sb + SS_BHI + off);
                ldsm4(bl[jj*2][0], bl[jj*2][1], bl[jj*2+1][0], bl[jj*2+1][1], sb + SS_BLO + off);
            }
            #pragma unroll
            for (int i = 0; i < 2; i++)
                #pragma unroll
                for (int j = 0; j < 4; j++) {
                    mma16816(acc[i][j], ah[i], bh[j]);
                    mma16816(acc[i][j], ah[i], bl[j]);
                    mma16816(acc[i][j], al[i], bh[j]);
                }
        }

        // Epilogue: mask + scale -> g_s
        #pragma unroll
        for (int i = 0; i < 2; i++)
            #pragma unroll
            for (int j = 0; j < 4; j++) {
                int q = q0 + mw * 32 + i * 16 + gid;
                int c = kc + nw * 32 + j * 8 + tg * 2;
                const size_t mrow0 = (size_t)(b3 * QLL + q) * KLL + c;
                const size_t srow0 = ((size_t)bh * QLL + q) * KLL + c;
                int2 mk = *reinterpret_cast<const int2*>(mask + mrow0);
                *reinterpret_cast<float2*>(g_s + srow0) = make_float2(
                    mk.x ? -1e9f : acc[i][j][0] * SCALEF,
                    mk.y ? -1e9f : acc[i][j][1] * SCALEF);
                mk = *reinterpret_cast<const int2*>(mask + mrow0 + 8 * KLL);
                *reinterpret_cast<float2*>(g_s + srow0 + 8 * KLL) = make_float2(
                    mk.x ? -1e9f : acc[i][j][2] * SCALEF,
                    mk.y ? -1e9f : acc[i][j][3] * SCALEF);
            }
        __syncthreads();
    }
}

// ---------------------------------------------------------------------------
// Softmax: one block per (b,h,q) row of 2048; values stay in registers.
// ---------------------------------------------------------------------------
__device__ __forceinline__ float warp_max(float v) {
    #pragma unroll
    for (int o = 16; o; o >>= 1) v = fmaxf(v, __shfl_xor_sync(0xffffffffu, v, o));
    return v;
}
__device__ __forceinline__ float warp_sum(float v) {
    #pragma unroll
    for (int o = 16; o; o >>= 1) v += __shfl_xor_sync(0xffffffffu, v, o);
    return v;
}

__global__ __launch_bounds__(256)
void softmax_kernel(const float* __restrict__ S, float* __restrict__ P)
{
    const size_t row = blockIdx.x;
    const float* s = S + row * KLL;
    float*       p = P + row * KLL;

    __shared__ float sh[8];
    const int wid = threadIdx.x >> 5;
    const int lid = threadIdx.x & 31;

    float v[8];
    float m = -3.0e38f;
    #pragma unroll
    for (int i = 0; i < 8; i++) {
        v[i] = s[threadIdx.x + i * 256];
        m = fmaxf(m, v[i]);
    }
    float wm = warp_max(m);
    if (lid == 0) sh[wid] = wm;
    __syncthreads();
    if (wid == 0) {
        float t = (lid < 8) ? sh[lid] : -3.0e38f;
        t = warp_max(t);
        if (lid == 0) sh[0] = t;
    }
    __syncthreads();
    const float bm = sh[0];

    float lsum = 0.0f;
    #pragma unroll
    for (int i = 0; i < 8; i++) {
        v[i] = __expf(v[i] - bm);
        lsum += v[i];
    }
    float ws = warp_sum(lsum);
    __syncthreads();
    if (lid == 0) sh[wid] = ws;
    __syncthreads();
    if (wid == 0) {
        float t = (lid < 8) ? sh[lid] : 0.0f;
        t = warp_sum(t);
        if (lid == 0) sh[0] = t;
    }
    __syncthreads();
    const float inv = 1.0f / sh[0];

    #pragma unroll
    for (int i = 0; i < 8; i++)
        p[threadIdx.x + i * 256] = v[i] * inv;
}

// ---------------------------------------------------------------------------
// Launch
// ---------------------------------------------------------------------------
extern "C" void kernel_launch(void* const* d_in, const int* in_sizes, int n_in,
                              void* d_out, int out_size)
{
    (void)in_sizes; (void)n_in; (void)out_size;

    const float*  Q    = (const float*)d_in[0];
    const float*  Kin  = (const float*)d_in[1];
    const float*  Vin  = (const float*)d_in[2];
    const float*  pos  = (const float*)d_in[3];
    const float*  rwb  = (const float*)d_in[4];
    const float*  rrb  = (const float*)d_in[5];
    const mask_t* mask = (const mask_t*)d_in[6];
    // d_in[7] = mems (unused)
    const float*  Wq = (const float*)d_in[8];
    const float*  bq = (const float*)d_in[9];
    const float*  Wk = (const float*)d_in[10];
    const float*  bk = (const float*)d_in[11];
    const float*  Wv = (const float*)d_in[12];
    const float*  bv = (const float*)d_in[13];
    const float*  Wr = (const float*)d_in[14];
    const float*  Wo = (const float*)d_in[15];
    const float*  bo = (const float*)d_in[16];

    float* out  = (float*)d_out;
    float* prob = out + (size_t)BB * QLL * EE;

    float *pq, *pk, *pv, *pr, *ps, *pvec;
    cudaGetSymbolAddress((void**)&pq,   g_q);
    cudaGetSymbolAddress((void**)&pk,   g_k);
    cudaGetSymbolAddress((void**)&pv,   g_v);
    cudaGetSymbolAddress((void**)&pr,   g_r);
    cudaGetSymbolAddress((void**)&ps,   g_s);
    cudaGetSymbolAddress((void**)&pvec, g_vec);

    cudaFuncSetAttribute(tgemm,  cudaFuncAttributeMaxDynamicSharedMemorySize, SM_G_TOTAL);
    cudaFuncSetAttribute(tscore, cudaFuncAttributeMaxDynamicSharedMemorySize, SS_TOTAL);

    const dim3 blk(256);

    // Projections: C = A @ W + b   (B element (n,k) = W[k*N + n])
    tgemm<<<dim3(HDD / 64, (BB * QLL) / 128, 1), blk, SM_G_TOTAL>>>(
        Q,   EE, 0, 0,  Wq, HDD, 0, 0,  bq,      pq, HDD, 0, 0,  EE, 1);
    tgemm<<<dim3(HDD / 64, (BB * KLL) / 128, 1), blk, SM_G_TOTAL>>>(
        Kin, EE, 0, 0,  Wk, HDD, 0, 0,  bk,      pk, HDD, 0, 0,  EE, 1);
    tgemm<<<dim3(HDD / 64, (BB * KLL) / 128, 1), blk, SM_G_TOTAL>>>(
        Vin, EE, 0, 0,  Wv, HDD, 0, 0,  bv,      pv, HDD, 0, 0,  EE, 1);
    tgemm<<<dim3(HDD / 64, KLL / 128, 1), blk, SM_G_TOTAL>>>(
        pos, EE, 0, 0,  Wr, HDD, 0, 0,  nullptr, pr, HDD, 0, 0,  EE, 1);

    // Scores (fused AC + rel-shifted BD, mask, scale)
    tscore<<<dim3(1, QLL / 128, BB * HH), blk, SS_TOTAL>>>(rwb, rrb, mask);

    // Softmax -> prob output region
    softmax_kernel<<<BB * HH * QLL, blk>>>(ps, prob);

    // PV: per (b,h): vec = prob @ V_h
    tgemm<<<dim3(1, QLL / 128, BB * HH), blk, SM_G_TOTAL>>>(
        prob, KLL, (long)HH * QLL * KLL, (long)QLL * KLL,
        pv,   HDD, (long)KLL * HDD,      (long)DD,
        nullptr,
        pvec, HDD, (long)QLL * HDD,      (long)DD,
        KLL, HH);

    // Output projection
    tgemm<<<dim3(EE / 64, (BB * QLL) / 128, 1), blk, SM_G_TOTAL>>>(
        pvec, HDD, 0, 0,  Wo, EE, 0, 0,  bo,  out, EE, 0, 0,  HDD, 1);
}